// round 13
// baseline (speedup 1.0000x reference)
#include <cuda_runtime.h>
#include <cuda_bf16.h>
#include <math.h>

// WaveletAttention: out = x * sigmoid(relu(mean(dwt2_ll(x)) @ W1^T) @ W2^T)
// x [8,256,256,256] f32 (512 MB), W1 [16,256], W2 [256,16].
//
// mean(dwt2_ll(x)) == (1/135^2) * sum_{i,j} w[i]*w[j]*x[b,c,i,j]  (linear +
// separable), w = fixed 256-weight vector from db8 dec_lo, symmetric pad.
//
// R13 = R12 (2-kernel streaming, evict-first head + evict-last 112 MB tail,
// reverse-order harvest: 253.1 us) + PDL overlap of the inter-kernel gap:
//   reduce triggers programmatic launch after its load loop; scale starts
//   while reduce drains, issues its first x loads (independent of g_y),
//   then cudaGridDependencySynchronize() before the FC reads g_y.

#define PLANE      65536       // floats per 256x256 plane
#define PLANE4     16384       // float4 per plane
#define NBC        2048
#define INV_MEAN   (1.0f/(135.0f*135.0f))
#define TAIL_START 1600        // 448 pinned planes = 112 MB (L2 = 126 MB)

__device__ float g_y[NBC];     // weighted spatial means

// pywt db8 dec_lo, 16 taps
__constant__ float c_f[16] = {
    -0.00011747678400228192f, 0.0006754494059985568f, -0.0003917403729959771f,
    -0.00487035299301066f, 0.008746094047015655f, 0.013981027917015516f,
    -0.04408825393106472f, -0.01736930100202211f, 0.128747426620186f,
    0.00047248457399797254f, -0.2840155429624281f, -0.015829105256023893f,
    0.5853546836548691f, 0.6756307362980128f, 0.3128715909144659f,
    0.05441584224308161f
};

__device__ __forceinline__ float wcontrib(int q) {
    float s = 0.f;
#pragma unroll
    for (int k = 0; k < 16; ++k) {
        int qk = q + k;
        bool ok = ((qk & 1) == 0) && (qk >= 16) && (qk <= 284);
        s += ok ? c_f[k] : 0.f;
    }
    return s;
}
__device__ __forceinline__ float weight_at(int i) {
    return wcontrib(i + 15) + wcontrib(14 - i) + wcontrib(526 - i);
}

// 32-byte (8-float) load pinned to L2 with evict_last (only encodable form).
__device__ __forceinline__ void ldg_el8(const float* p, float* v) {
    unsigned long long x0, x1, x2, x3;
    asm volatile("ld.global.L2::evict_last.v4.b64 {%0,%1,%2,%3}, [%4];"
                 : "=l"(x0), "=l"(x1), "=l"(x2), "=l"(x3) : "l"(p));
    v[0] = __uint_as_float((unsigned)x0); v[1] = __uint_as_float((unsigned)(x0 >> 32));
    v[2] = __uint_as_float((unsigned)x1); v[3] = __uint_as_float((unsigned)(x1 >> 32));
    v[4] = __uint_as_float((unsigned)x2); v[5] = __uint_as_float((unsigned)(x2 >> 32));
    v[6] = __uint_as_float((unsigned)x3); v[7] = __uint_as_float((unsigned)(x3 >> 32));
}

// ---------------------------------------------------------------------------
// Kernel 1: per-(b,c) weighted spatial reduction. One block per plane.
// Head planes evict-first; tail planes pinned evict-last (32B loads).
// Triggers programmatic launch of the scale kernel after its load loop.
// ---------------------------------------------------------------------------
__global__ void __launch_bounds__(256) reduce_kernel(const float* __restrict__ x) {
    __shared__ float sw[256];
    __shared__ float red[8];
    const int t = threadIdx.x;

    sw[t] = weight_at(t);
    __syncthreads();

    const int bc = blockIdx.x;
    float acc = 0.f;

    if (bc >= TAIL_START) {
        const float* __restrict__ pf = x + (size_t)bc * PLANE;
        const int cb = (t & 31) * 8;
        float wc[8];
#pragma unroll
        for (int j = 0; j < 8; ++j) wc[j] = sw[cb + j];
        const int rbase = t >> 5;
#pragma unroll 4
        for (int it = 0; it < 32; ++it) {
            float v[8];
            ldg_el8(pf + it * 2048 + t * 8, v);      // pin in L2
            float wi = sw[it * 8 + rbase];
            float d = wc[0] * v[0] + wc[1] * v[1] + wc[2] * v[2] + wc[3] * v[3]
                    + wc[4] * v[4] + wc[5] * v[5] + wc[6] * v[6] + wc[7] * v[7];
            acc += wi * d;
        }
    } else {
        const float4* __restrict__ p = (const float4*)x + (size_t)bc * PLANE4;
        const int jc = (t & 63) * 4;
        const float w0 = sw[jc], w1 = sw[jc + 1], w2 = sw[jc + 2], w3 = sw[jc + 3];
        const int ibase = t >> 6;
#pragma unroll 8
        for (int it = 0; it < 64; ++it) {
            float4 v = __ldcs(p + it * 256 + t);     // evict-first
            float wi = sw[ibase + it * 4];
            acc += wi * (w0 * v.x + w1 * v.y + w2 * v.z + w3 * v.w);
        }
    }

    cudaTriggerProgrammaticLaunchCompletion();        // let scale grid launch

#pragma unroll
    for (int o = 16; o; o >>= 1) acc += __shfl_down_sync(0xffffffffu, acc, o);
    if ((t & 31) == 0) red[t >> 5] = acc;
    __syncthreads();
    if (t < 8) {
        float v = red[t];
#pragma unroll
        for (int o = 4; o; o >>= 1) v += __shfl_down_sync(0xffu, v, o);
        if (t == 0) g_y[bc] = v * INV_MEAN;
    }
}

// ---------------------------------------------------------------------------
// Kernel 2: fused FC + scale (PDL secondary). Grid 8192 x 256 thr.
// bc DESCENDING: first waves consume the pinned L2 tail. First 8 float4
// loads of x issued BEFORE the grid-dependency sync (independent of g_y).
// ---------------------------------------------------------------------------
__global__ void __launch_bounds__(256) scale_kernel(const float* __restrict__ x,
                                                    float* __restrict__ out,
                                                    const float* __restrict__ W1,
                                                    const float* __restrict__ W2) {
    __shared__ float red[256];
    __shared__ float sh_h[16];

    const int t = threadIdx.x;
    const int bid = blockIdx.x;
    const int bc = (NBC - 1) - (bid >> 2);   // reverse plane order
    const int chunk = bid & 3;
    const int b = bc >> 8, c = bc & 255;

    const size_t base = (size_t)bc * PLANE4 + chunk * 4096 + t;
    const float4* __restrict__ px = (const float4*)x + base;
    float4* __restrict__ po = (float4*)out + base;

    // Overlap: issue first half of the x reads before depending on reduce.
    float4 v[8];
#pragma unroll
    for (int j = 0; j < 8; ++j) v[j] = __ldcs(px + j * 256);

    cudaGridDependencySynchronize();         // g_y now complete & visible

    // ---- inline FC: h[u] = relu(sum_c y[b,c]*W1[u,c]); s = sigmoid(h.W2[c]) ----
    {
        const float* yb = g_y + b * 256;
        const int u = t >> 4, k = t & 15;
        const float* w1p = W1 + u * 256 + k * 16;
        const float* yy = yb + k * 16;
        float part = 0.f;
#pragma unroll
        for (int j = 0; j < 16; ++j) part += yy[j] * w1p[j];
        red[t] = part;
        __syncthreads();
        if (t < 16) {
            float s = 0.f;
#pragma unroll
            for (int j = 0; j < 16; ++j) s += red[t * 16 + j];
            sh_h[t] = fmaxf(s, 0.f);
        }
        __syncthreads();
    }
    float sv = 0.f;
    {
        const float* w2p = W2 + c * 16;
#pragma unroll
        for (int u = 0; u < 16; ++u) sv += sh_h[u] * w2p[u];
        sv = 1.f / (1.f + expf(-sv));
    }

#pragma unroll
    for (int j = 0; j < 8; ++j) {
        v[j].x *= sv; v[j].y *= sv; v[j].z *= sv; v[j].w *= sv;
        __stcs(po + j * 256, v[j]);
    }
#pragma unroll
    for (int j = 8; j < 16; ++j) {
        float4 w = __ldcs(px + j * 256);
        w.x *= sv; w.y *= sv; w.z *= sv; w.w *= sv;
        __stcs(po + j * 256, w);
    }
}

extern "C" void kernel_launch(void* const* d_in, const int* in_sizes, int n_in,
                              void* d_out, int out_size) {
    const float* x  = (const float*)d_in[0];
    const float* W1 = (const float*)d_in[1];   // [16,256]
    const float* W2 = (const float*)d_in[2];   // [256,16]
    float* out = (float*)d_out;

    reduce_kernel<<<NBC, 256>>>(x);

    // Scale kernel as PDL secondary: may launch once all reduce blocks have
    // triggered; memory dependency enforced inside via GridDependencySync.
    cudaLaunchAttribute attr[1];
    attr[0].id = cudaLaunchAttributeProgrammaticStreamSerialization;
    attr[0].val.programmaticStreamSerializationAllowed = 1;
    cudaLaunchConfig_t cfg = {};
    cfg.gridDim = dim3(NBC * 4);
    cfg.blockDim = dim3(256);
    cfg.dynamicSmemBytes = 0;
    cfg.stream = 0;
    cfg.attrs = attr;
    cfg.numAttrs = 1;
    cudaLaunchKernelEx(&cfg, scale_kernel, x, out, W1, W2);
}

// round 14
// speedup vs baseline: 1.0945x; 1.0945x over previous
#include <cuda_runtime.h>
#include <cuda_bf16.h>
#include <math.h>

// WaveletAttention: out = x * sigmoid(relu(mean(dwt2_ll(x)) @ W1^T) @ W2^T)
// x [8,256,256,256] f32 (512 MB), W1 [16,256], W2 [256,16].
//
// mean(dwt2_ll(x)) == (1/135^2) * sum_{i,j} w[i]*w[j]*x[b,c,i,j]  (linear +
// separable), w = fixed 256-weight vector from db8 dec_lo, symmetric pad.
//
// R14 = R12 (2-kernel streaming, evict-first head + evict-last 112 MB tail,
// reverse-order harvest: 253.1 us) + zero-cost PDL: the scale kernel is a
// PDL secondary with cudaGridDependencySynchronize() at the TOP (nothing
// live across it -> regs stay 40, occ 68%), hiding launch latency and
// reduce's drain wave. R13's mistake (8 float4 held across the sync,
// regs 64, occ 46%) is reverted.

#define PLANE      65536       // floats per 256x256 plane
#define PLANE4     16384       // float4 per plane
#define NBC        2048
#define INV_MEAN   (1.0f/(135.0f*135.0f))
#define TAIL_START 1600        // 448 pinned planes = 112 MB (L2 = 126 MB)

__device__ float g_y[NBC];     // weighted spatial means

// pywt db8 dec_lo, 16 taps
__constant__ float c_f[16] = {
    -0.00011747678400228192f, 0.0006754494059985568f, -0.0003917403729959771f,
    -0.00487035299301066f, 0.008746094047015655f, 0.013981027917015516f,
    -0.04408825393106472f, -0.01736930100202211f, 0.128747426620186f,
    0.00047248457399797254f, -0.2840155429624281f, -0.015829105256023893f,
    0.5853546836548691f, 0.6756307362980128f, 0.3128715909144659f,
    0.05441584224308161f
};

__device__ __forceinline__ float wcontrib(int q) {
    float s = 0.f;
#pragma unroll
    for (int k = 0; k < 16; ++k) {
        int qk = q + k;
        bool ok = ((qk & 1) == 0) && (qk >= 16) && (qk <= 284);
        s += ok ? c_f[k] : 0.f;
    }
    return s;
}
__device__ __forceinline__ float weight_at(int i) {
    return wcontrib(i + 15) + wcontrib(14 - i) + wcontrib(526 - i);
}

// 32-byte (8-float) load pinned to L2 with evict_last (only encodable form).
__device__ __forceinline__ void ldg_el8(const float* p, float* v) {
    unsigned long long x0, x1, x2, x3;
    asm volatile("ld.global.L2::evict_last.v4.b64 {%0,%1,%2,%3}, [%4];"
                 : "=l"(x0), "=l"(x1), "=l"(x2), "=l"(x3) : "l"(p));
    v[0] = __uint_as_float((unsigned)x0); v[1] = __uint_as_float((unsigned)(x0 >> 32));
    v[2] = __uint_as_float((unsigned)x1); v[3] = __uint_as_float((unsigned)(x1 >> 32));
    v[4] = __uint_as_float((unsigned)x2); v[5] = __uint_as_float((unsigned)(x2 >> 32));
    v[6] = __uint_as_float((unsigned)x3); v[7] = __uint_as_float((unsigned)(x3 >> 32));
}

// ---------------------------------------------------------------------------
// Kernel 1: per-(b,c) weighted spatial reduction. One block per plane.
// Head planes evict-first; tail planes pinned evict-last (32B loads).
// Triggers programmatic launch of the scale kernel after its load loop.
// ---------------------------------------------------------------------------
__global__ void __launch_bounds__(256) reduce_kernel(const float* __restrict__ x) {
    __shared__ float sw[256];
    __shared__ float red[8];
    const int t = threadIdx.x;

    sw[t] = weight_at(t);
    __syncthreads();

    const int bc = blockIdx.x;
    float acc = 0.f;

    if (bc >= TAIL_START) {
        const float* __restrict__ pf = x + (size_t)bc * PLANE;
        const int cb = (t & 31) * 8;
        float wc[8];
#pragma unroll
        for (int j = 0; j < 8; ++j) wc[j] = sw[cb + j];
        const int rbase = t >> 5;
#pragma unroll 4
        for (int it = 0; it < 32; ++it) {
            float v[8];
            ldg_el8(pf + it * 2048 + t * 8, v);      // pin in L2
            float wi = sw[it * 8 + rbase];
            float d = wc[0] * v[0] + wc[1] * v[1] + wc[2] * v[2] + wc[3] * v[3]
                    + wc[4] * v[4] + wc[5] * v[5] + wc[6] * v[6] + wc[7] * v[7];
            acc += wi * d;
        }
    } else {
        const float4* __restrict__ p = (const float4*)x + (size_t)bc * PLANE4;
        const int jc = (t & 63) * 4;
        const float w0 = sw[jc], w1 = sw[jc + 1], w2 = sw[jc + 2], w3 = sw[jc + 3];
        const int ibase = t >> 6;
#pragma unroll 8
        for (int it = 0; it < 64; ++it) {
            float4 v = __ldcs(p + it * 256 + t);     // evict-first
            float wi = sw[ibase + it * 4];
            acc += wi * (w0 * v.x + w1 * v.y + w2 * v.z + w3 * v.w);
        }
    }

    cudaTriggerProgrammaticLaunchCompletion();        // let scale grid launch

#pragma unroll
    for (int o = 16; o; o >>= 1) acc += __shfl_down_sync(0xffffffffu, acc, o);
    if ((t & 31) == 0) red[t >> 5] = acc;
    __syncthreads();
    if (t < 8) {
        float v = red[t];
#pragma unroll
        for (int o = 4; o; o >>= 1) v += __shfl_down_sync(0xffu, v, o);
        if (t == 0) g_y[bc] = v * INV_MEAN;
    }
}

// ---------------------------------------------------------------------------
// Kernel 2: fused FC + scale (PDL secondary, sync at top — R12 body).
// Grid 8192 x 256 thr; 16 float4/thread. bc DESCENDING: first waves
// consume the pinned L2 tail.
// ---------------------------------------------------------------------------
__global__ void __launch_bounds__(256) scale_kernel(const float* __restrict__ x,
                                                    float* __restrict__ out,
                                                    const float* __restrict__ W1,
                                                    const float* __restrict__ W2) {
    __shared__ float red[256];
    __shared__ float sh_h[16];

    cudaGridDependencySynchronize();          // nothing live across this

    const int t = threadIdx.x;
    const int bid = blockIdx.x;
    const int bc = (NBC - 1) - (bid >> 2);    // reverse plane order
    const int chunk = bid & 3;
    const int b = bc >> 8, c = bc & 255;

    // ---- inline FC: h[u] = relu(sum_c y[b,c]*W1[u,c]); s = sigmoid(h.W2[c]) ----
    {
        const float* yb = g_y + b * 256;
        const int u = t >> 4, k = t & 15;
        const float* w1p = W1 + u * 256 + k * 16;
        const float* yy = yb + k * 16;
        float part = 0.f;
#pragma unroll
        for (int j = 0; j < 16; ++j) part += yy[j] * w1p[j];
        red[t] = part;
        __syncthreads();
        if (t < 16) {
            float s = 0.f;
#pragma unroll
            for (int j = 0; j < 16; ++j) s += red[t * 16 + j];
            sh_h[t] = fmaxf(s, 0.f);
        }
        __syncthreads();
    }
    float sv = 0.f;
    {
        const float* w2p = W2 + c * 16;
#pragma unroll
        for (int u = 0; u < 16; ++u) sv += sh_h[u] * w2p[u];
        sv = 1.f / (1.f + expf(-sv));
    }

    const size_t base = (size_t)bc * PLANE4 + chunk * 4096 + t;
    const float4* __restrict__ px = (const float4*)x + base;
    float4* __restrict__ po = (float4*)out + base;

#pragma unroll
    for (int k = 0; k < 16; k += 8) {
        float4 v[8];
#pragma unroll
        for (int j = 0; j < 8; ++j) v[j] = __ldcs(px + (k + j) * 256);
#pragma unroll
        for (int j = 0; j < 8; ++j) {
            v[j].x *= sv; v[j].y *= sv; v[j].z *= sv; v[j].w *= sv;
            __stcs(po + (k + j) * 256, v[j]);
        }
    }
}

extern "C" void kernel_launch(void* const* d_in, const int* in_sizes, int n_in,
                              void* d_out, int out_size) {
    const float* x  = (const float*)d_in[0];
    const float* W1 = (const float*)d_in[1];   // [16,256]
    const float* W2 = (const float*)d_in[2];   // [256,16]
    float* out = (float*)d_out;

    reduce_kernel<<<NBC, 256>>>(x);

    cudaLaunchAttribute attr[1];
    attr[0].id = cudaLaunchAttributeProgrammaticStreamSerialization;
    attr[0].val.programmaticStreamSerializationAllowed = 1;
    cudaLaunchConfig_t cfg = {};
    cfg.gridDim = dim3(NBC * 4);
    cfg.blockDim = dim3(256);
    cfg.dynamicSmemBytes = 0;
    cfg.stream = 0;
    cfg.attrs = attr;
    cfg.numAttrs = 1;
    cudaLaunchKernelEx(&cfg, scale_kernel, x, out, W1, W2);
}